// round 3
// baseline (speedup 1.0000x reference)
#include <cuda_runtime.h>
#include <cstdint>
#include <cstddef>

// Problem dims (fixed by the dataset)
#define E_DIM 16
#define B_DIM 128
#define C_DIM 512
#define H_DIM 1024
#define D_DIM 130
#define DPAD  132            // D padded to mult of 4 (16B rows)
#define S_DIM 16
#define NROW  2048           // E*B
#define G3    3072           // 3*H
#define TROW  32768          // S*NROW
#define OUT_T 256            // E*S_DIM

// ---------------- scratch (static device globals; no allocation) -------------
__device__ __align__(16) float g_H1[NROW * H_DIM];
__device__ __align__(16) float g_H2[NROW * H_DIM];
__device__ __align__(16) float g_TA[NROW * G3];
__device__ __align__(16) float g_TB[NROW * G3];
__device__ __align__(16) float g_CP[NROW * G3];
__device__ __align__(16) float g_T0[NROW * 2 * H_DIM];
__device__ __align__(16) float g_PREV[(size_t)S_DIM * NROW * DPAD];
__device__ __align__(16) float g_PP[(size_t)S_DIM * NROW * G3];
__device__ __align__(16) float g_HA[(size_t)S_DIM * NROW * H_DIM];
__device__ __align__(16) float g_Y[(size_t)TROW * D_DIM];
__device__ __align__(16) float g_W1C[G3 * C_DIM];   // g1_wih[:, :C] repacked
__device__ __align__(16) float g_W1P[G3 * DPAD];    // g1_wih[:, C:] repacked+padded

// ---------------- TF32 helpers ----------------------------------------------
__device__ __forceinline__ float f2tf32(float x) {
    unsigned r;
    asm("cvt.rna.tf32.f32 %0, %1;" : "=r"(r) : "f"(x));
    return __uint_as_float(r);
}

__device__ __forceinline__ void mma_tf32(float d[4], const unsigned a[4],
                                         const unsigned b[2]) {
    asm volatile(
        "mma.sync.aligned.m16n8k8.row.col.f32.tf32.tf32.f32 "
        "{%0,%1,%2,%3}, {%4,%5,%6,%7}, {%8,%9}, {%0,%1,%2,%3};\n"
        : "+f"(d[0]), "+f"(d[1]), "+f"(d[2]), "+f"(d[3])
        : "r"(a[0]), "r"(a[1]), "r"(a[2]), "r"(a[3]),
          "r"(b[0]), "r"(b[1]));
}

// ---------------- TN GEMM, register double-buffered, batched via blockIdx.z --
// C[M,N] = A[M,K] * B[N,K]^T (+bias[n]).  BM=BN=128, BK=16, 256 thr, 8 warps.
#define BM 128
#define BN 128
#define BK 16
#define SROW 20            // BK + 4 pad: conflict-free fragment LDS
#define ASZ (BM * SROW)

template <bool HAS_BIAS>
__global__ __launch_bounds__(256, 2) void gemm_tn(
    const float* __restrict__ A0, const float* __restrict__ A1, int lda,
    const float* __restrict__ B0, const float* __restrict__ B1, int ldb,
    const float* __restrict__ bias0, const float* __restrict__ bias1,
    float* __restrict__ C0, float* __restrict__ C1, int ldc,
    int M, int N, int K)
{
    __shared__ __align__(16) float sm[2 * 2 * ASZ];

    const float* A    = blockIdx.z ? A1 : A0;
    const float* B    = blockIdx.z ? B1 : B0;
    const float* bias = blockIdx.z ? bias1 : bias0;
    float*       C    = blockIdx.z ? C1 : C0;

    const int tid  = threadIdx.x;
    const int lane = tid & 31;
    const int warp = tid >> 5;
    const int wm   = (warp & 1) * 64;
    const int wn   = (warp >> 1) * 32;
    const int g    = lane >> 2;
    const int tg   = lane & 3;
    const int bm0  = blockIdx.y * BM;
    const int bn0  = blockIdx.x * BN;

    float acc[4][4][4];
#pragma unroll
    for (int mi = 0; mi < 4; mi++)
#pragma unroll
        for (int ni = 0; ni < 4; ni++)
#pragma unroll
            for (int f = 0; f < 4; f++) acc[mi][ni][f] = 0.f;

    const int KT = (K + BK - 1) / BK;
    float4 ra[2], rb[2];
    const float4 z4 = make_float4(0.f, 0.f, 0.f, 0.f);

    // -------- load tile kt into registers --------
#define LOAD_TILE(kt)                                                         \
    {                                                                         \
        _Pragma("unroll") for (int i = 0; i < 2; i++) {                       \
            int f = i * 256 + tid;                                            \
            int r = f >> 2, cg = f & 3;                                       \
            int gc = (kt) * BK + cg * 4;                                      \
            ra[i] = (gc < K)                                                  \
                ? *(const float4*)(A + (size_t)(bm0 + r) * lda + gc) : z4;    \
            int gr = bn0 + r;                                                 \
            rb[i] = (gc < K && gr < N)                                        \
                ? *(const float4*)(B + (size_t)gr * ldb + gc) : z4;           \
        }                                                                     \
    }

    // -------- convert + store registers to smem stage st --------
#define STS_TILE(st)                                                          \
    {                                                                         \
        float* As = sm + (st) * 2 * ASZ;                                      \
        float* Bs = As + ASZ;                                                 \
        _Pragma("unroll") for (int i = 0; i < 2; i++) {                       \
            int f = i * 256 + tid;                                            \
            int r = f >> 2, cg = f & 3;                                       \
            float4 a = ra[i], b = rb[i];                                      \
            a.x = f2tf32(a.x); a.y = f2tf32(a.y);                             \
            a.z = f2tf32(a.z); a.w = f2tf32(a.w);                             \
            b.x = f2tf32(b.x); b.y = f2tf32(b.y);                             \
            b.z = f2tf32(b.z); b.w = f2tf32(b.w);                             \
            *(float4*)(As + r * SROW + cg * 4) = a;                           \
            *(float4*)(Bs + r * SROW + cg * 4) = b;                           \
        }                                                                     \
    }

    // -------- compute on smem stage st --------
#define COMP_TILE(st)                                                         \
    {                                                                         \
        const float* As = sm + (st) * 2 * ASZ;                                \
        const float* Bs = As + ASZ;                                           \
        _Pragma("unroll") for (int ks = 0; ks < 2; ks++) {                    \
            const int k0 = ks * 8;                                            \
            unsigned af[4][4], bf[4][2];                                      \
            _Pragma("unroll") for (int mi = 0; mi < 4; mi++) {                \
                const int rbase = wm + mi * 16;                               \
                af[mi][0] = __float_as_uint(As[(rbase + g) * SROW + k0 + tg]);       \
                af[mi][1] = __float_as_uint(As[(rbase + g + 8) * SROW + k0 + tg]);   \
                af[mi][2] = __float_as_uint(As[(rbase + g) * SROW + k0 + tg + 4]);   \
                af[mi][3] = __float_as_uint(As[(rbase + g + 8) * SROW + k0 + tg + 4]);\
            }                                                                 \
            _Pragma("unroll") for (int ni = 0; ni < 4; ni++) {                \
                const int nb = wn + ni * 8;                                   \
                bf[ni][0] = __float_as_uint(Bs[(nb + g) * SROW + k0 + tg]);      \
                bf[ni][1] = __float_as_uint(Bs[(nb + g) * SROW + k0 + tg + 4]);  \
            }                                                                 \
            _Pragma("unroll") for (int mi = 0; mi < 4; mi++)                  \
                _Pragma("unroll") for (int ni = 0; ni < 4; ni++)              \
                    mma_tf32(acc[mi][ni], af[mi], bf[ni]);                    \
        }                                                                     \
    }

    LOAD_TILE(0);
    STS_TILE(0);
    __syncthreads();
    int cur = 0;
    for (int kt = 1; kt < KT; kt++) {
        LOAD_TILE(kt);
        COMP_TILE(cur);
        STS_TILE(cur ^ 1);
        __syncthreads();
        cur ^= 1;
    }
    COMP_TILE(cur);

#undef LOAD_TILE
#undef STS_TILE
#undef COMP_TILE

    // -------- epilogue --------
#pragma unroll
    for (int mi = 0; mi < 4; mi++) {
        const int r0 = bm0 + wm + mi * 16 + g;   // M is always a mult of 128
#pragma unroll
        for (int ni = 0; ni < 4; ni++) {
            const int c0 = bn0 + wn + ni * 8 + 2 * tg;
            float b0 = 0.f, b1 = 0.f;
            if (HAS_BIAS) {
                if (c0 < N)     b0 = bias[c0];
                if (c0 + 1 < N) b1 = bias[c0 + 1];
            }
            if (c0 < N)     C[(size_t)r0 * ldc + c0]           = acc[mi][ni][0] + b0;
            if (c0 + 1 < N) C[(size_t)r0 * ldc + c0 + 1]       = acc[mi][ni][1] + b1;
            if (c0 < N)     C[(size_t)(r0 + 8) * ldc + c0]     = acc[mi][ni][2] + b0;
            if (c0 + 1 < N) C[(size_t)(r0 + 8) * ldc + c0 + 1] = acc[mi][ni][3] + b1;
        }
    }
}

// ---------------- elementwise kernels (float4) -------------------------------
__device__ __forceinline__ float sigf(float x) {
    return 1.f / (1.f + __expf(-x));
}

// gi = gi1 (+gi2); h' = (1-z)*n + z*h. One float4 = 4 hidden units.
template <bool HAS_GI2, bool HAS_COPY>
__global__ void gate_kernel(const float4* __restrict__ gi1,
                            const float4* __restrict__ gi2,
                            const float4* __restrict__ gh,
                            float4* __restrict__ h,
                            float4* __restrict__ hcopy)
{
    int v = blockIdx.x * blockDim.x + threadIdx.x;   // NROW*H/4 threads
    int m = v >> 8, q = v & 255;                     // H/4 = 256
    int base = m * 768 + q;                          // G3/4 = 768
    float4 ir = gi1[base], iz = gi1[base + 256], in = gi1[base + 512];
    if (HAS_GI2) {
        float4 a = gi2[base], b = gi2[base + 256], c = gi2[base + 512];
        ir.x += a.x; ir.y += a.y; ir.z += a.z; ir.w += a.w;
        iz.x += b.x; iz.y += b.y; iz.z += b.z; iz.w += b.w;
        in.x += c.x; in.y += c.y; in.z += c.z; in.w += c.w;
    }
    float4 hr = gh[base], hz = gh[base + 256], hn = gh[base + 512];
    float4 hv = h[v];
    float4 o;
    {
        float r = sigf(ir.x + hr.x), z = sigf(iz.x + hz.x);
        float n = tanhf(in.x + r * hn.x);
        o.x = (1.f - z) * n + z * hv.x;
    }
    {
        float r = sigf(ir.y + hr.y), z = sigf(iz.y + hz.y);
        float n = tanhf(in.y + r * hn.y);
        o.y = (1.f - z) * n + z * hv.y;
    }
    {
        float r = sigf(ir.z + hr.z), z = sigf(iz.z + hz.z);
        float n = tanhf(in.z + r * hn.z);
        o.z = (1.f - z) * n + z * hv.z;
    }
    {
        float r = sigf(ir.w + hr.w), z = sigf(iz.w + hz.w);
        float n = tanhf(in.w + r * hn.w);
        o.w = (1.f - z) * n + z * hv.w;
    }
    h[v] = o;
    if (HAS_COPY) hcopy[v] = o;
}

__global__ void init_tanh(const float4* __restrict__ t0,
                          float4* __restrict__ h1, float4* __restrict__ h2)
{
    int v = blockIdx.x * blockDim.x + threadIdx.x;   // NROW*H/4
    int m = v >> 8, q = v & 255;
    float4 a = t0[m * 512 + q];           // 2H/4 = 512
    float4 b = t0[m * 512 + 256 + q];
    a.x = tanhf(a.x); a.y = tanhf(a.y); a.z = tanhf(a.z); a.w = tanhf(a.w);
    b.x = tanhf(b.x); b.y = tanhf(b.y); b.z = tanhf(b.z); b.w = tanhf(b.w);
    h1[v] = a;
    h2[v] = b;
}

// PREV[s, e*B+b, d] (stride DPAD) = (t==0) ? 0 : target[b, t-1, d], t = e*S+s
__global__ void pack_prev(const float* __restrict__ target,
                          float* __restrict__ prev)
{
    int idx = blockIdx.x * blockDim.x + threadIdx.x;
    if (idx >= S_DIM * NROW * DPAD) return;
    int d = idx % DPAD;
    int r = (idx / DPAD) % NROW;
    int s = idx / (DPAD * NROW);
    int e = r >> 7, b = r & 127;
    int t = e * S_DIM + s;
    float val = 0.f;
    if (d < D_DIM && t != 0)
        val = target[((size_t)b * OUT_T + (t - 1)) * D_DIM + d];
    prev[idx] = val;
}

// repack g1_wih (row stride C+D=642) into W1C [3072x512] and W1P [3072x132]
__global__ void repack_w1(const float* __restrict__ w,
                          float* __restrict__ w1c, float* __restrict__ w1p)
{
    int idx = blockIdx.x * blockDim.x + threadIdx.x;
    const int T1 = G3 * C_DIM;
    const int T2 = G3 * DPAD;
    if (idx < T1) {
        int n = idx / C_DIM, k = idx % C_DIM;
        w1c[idx] = w[(size_t)n * (C_DIM + D_DIM) + k];
    } else if (idx < T1 + T2) {
        int j = idx - T1;
        int n = j / DPAD, k = j % DPAD;
        w1p[j] = (k < D_DIM) ? w[(size_t)n * (C_DIM + D_DIM) + C_DIM + k] : 0.f;
    }
}

// out[b, e*S+s, d] = Y[s*NROW + e*B + b, d]
__global__ void scatter_out(const float* __restrict__ y,
                            float* __restrict__ out)
{
    int idx = blockIdx.x * blockDim.x + threadIdx.x;
    if (idx >= TROW * D_DIM) return;
    int d = idx % D_DIM;
    int m = idx / D_DIM;
    int s = m >> 11;
    int r = m & 2047;
    int e = r >> 7, b = r & 127;
    out[((size_t)b * OUT_T + e * S_DIM + s) * D_DIM + d] = y[idx];
}

// ---------------- launch helpers ---------------------------------------------
static inline void gemm1(const float* A, int lda, const float* B, int ldb,
                         const float* bias, float* C, int ldc,
                         int M, int N, int K)
{
    dim3 grid((N + BN - 1) / BN, (M + BM - 1) / BM, 1);
    if (bias)
        gemm_tn<true><<<grid, 256>>>(A, A, lda, B, B, ldb, bias, bias,
                                     C, C, ldc, M, N, K);
    else
        gemm_tn<false><<<grid, 256>>>(A, A, lda, B, B, ldb, nullptr, nullptr,
                                      C, C, ldc, M, N, K);
}

static inline void gemm2(const float* A0, const float* A1, int lda,
                         const float* B0, const float* B1, int ldb,
                         const float* b0, const float* b1,
                         float* C0, float* C1, int ldc,
                         int M, int N, int K)
{
    dim3 grid((N + BN - 1) / BN, (M + BM - 1) / BM, 2);
    gemm_tn<true><<<grid, 256>>>(A0, A1, lda, B0, B1, ldb, b0, b1,
                                 C0, C1, ldc, M, N, K);
}

extern "C" void kernel_launch(void* const* d_in, const int* in_sizes, int n_in,
                              void* d_out, int out_size)
{
    const float* c      = (const float*)d_in[0];
    const float* target = (const float*)d_in[1];
    int base = (n_in >= 16) ? 4 : 2;
    const float* fc_init_w = (const float*)d_in[base + 0];
    const float* fc_init_b = (const float*)d_in[base + 1];
    const float* g1_wih    = (const float*)d_in[base + 2];
    const float* g1_whh    = (const float*)d_in[base + 3];
    const float* g1_bih    = (const float*)d_in[base + 4];
    const float* g1_bhh    = (const float*)d_in[base + 5];
    const float* g2_wih    = (const float*)d_in[base + 6];
    const float* g2_whh    = (const float*)d_in[base + 7];
    const float* g2_bih    = (const float*)d_in[base + 8];
    const float* g2_bhh    = (const float*)d_in[base + 9];
    const float* fco_w     = (const float*)d_in[base + 10];
    const float* fco_b     = (const float*)d_in[base + 11];
    float* out = (float*)d_out;

    float *H1, *H2, *TA, *TB, *CP, *T0, *PV, *PP, *HA, *Y, *W1C, *W1P;
    cudaGetSymbolAddress((void**)&H1, g_H1);
    cudaGetSymbolAddress((void**)&H2, g_H2);
    cudaGetSymbolAddress((void**)&TA, g_TA);
    cudaGetSymbolAddress((void**)&TB, g_TB);
    cudaGetSymbolAddress((void**)&CP, g_CP);
    cudaGetSymbolAddress((void**)&T0, g_T0);
    cudaGetSymbolAddress((void**)&PV, g_PREV);
    cudaGetSymbolAddress((void**)&PP, g_PP);
    cudaGetSymbolAddress((void**)&HA, g_HA);
    cudaGetSymbolAddress((void**)&Y,  g_Y);
    cudaGetSymbolAddress((void**)&W1C, g_W1C);
    cudaGetSymbolAddress((void**)&W1P, g_W1P);

    // ---- precompute (non-recurrent) ----
    repack_w1<<<(G3 * (C_DIM + DPAD) + 255) / 256, 256>>>(g1_wih, W1C, W1P);
    pack_prev<<<(S_DIM * NROW * DPAD + 255) / 256, 256>>>(target, PV);

    // cpart = cflat @ W1C^T + g1_bih        [2048 x 3072]
    gemm1(c, C_DIM, W1C, C_DIM, g1_bih, CP, G3, NROW, G3, C_DIM);
    // prevpart[s] = PREV[s] @ W1P^T         [32768 x 3072]
    gemm1(PV, DPAD, W1P, DPAD, nullptr, PP, G3, TROW, G3, DPAD);
    // t0 = c @ fc_init_w^T + fc_init_b      [2048 x 2048]
    gemm1(c, C_DIM, fc_init_w, C_DIM, fc_init_b, T0, 2 * H_DIM,
          NROW, 2 * H_DIM, C_DIM);
    init_tanh<<<(NROW * H_DIM / 4) / 256, 256>>>(
        (const float4*)T0, (float4*)H1, (float4*)H2);

    // ---- recurrent loop ----
    for (int s = 0; s < S_DIM; s++) {
        // gh1 = h1 @ g1_whh^T + g1_bhh ; gh2 = h2 @ g2_whh^T + g2_bhh (batched)
        gemm2(H1, H2, H_DIM, g1_whh, g2_whh, H_DIM, g1_bhh, g2_bhh,
              TA, TB, G3, NROW, G3, H_DIM);
        // gate1: h1' = GRU(cp+pp[s], gh1, h1)
        gate_kernel<true, false><<<(NROW * H_DIM / 4) / 256, 256>>>(
            (const float4*)CP, (const float4*)(PP + (size_t)s * NROW * G3),
            (const float4*)TA, (float4*)H1, nullptr);
        // gi2 = h1' @ g2_wih^T + g2_bih
        gemm1(H1, H_DIM, g2_wih, H_DIM, g2_bih, TA, G3, NROW, G3, H_DIM);
        // gate2: h2' = GRU(gi2, gh2, h2); also save to history
        gate_kernel<false, true><<<(NROW * H_DIM / 4) / 256, 256>>>(
            (const float4*)TA, nullptr, (const float4*)TB,
            (float4*)H2, (float4*)(HA + (size_t)s * NROW * H_DIM));
    }

    // ---- batched output projection + scatter ----
    gemm1(HA, H_DIM, fco_w, H_DIM, fco_b, Y, D_DIM, TROW, D_DIM, H_DIM);
    scatter_out<<<(TROW * D_DIM + 255) / 256, 256>>>(Y, out);
}

// round 5
// speedup vs baseline: 1.4330x; 1.4330x over previous
#include <cuda_runtime.h>
#include <cstdint>
#include <cstddef>

#define E_DIM 16
#define B_DIM 128
#define C_DIM 512
#define H_DIM 1024
#define D_DIM 130
#define DPAD  132
#define S_DIM 16
#define NROW  2048
#define G3    3072
#define TROW  32768
#define OUT_T 256

// ---------------- scratch (static device globals) ----------------------------
__device__ __align__(16) float g_H1[NROW * H_DIM];
__device__ __align__(16) float g_H2[NROW * H_DIM];
__device__ __align__(16) float g_TA[NROW * G3];
__device__ __align__(16) float g_TB[NROW * G3];
__device__ __align__(16) float g_PPs[NROW * G3];          // prev-part, this step
__device__ __align__(16) float g_CP[NROW * G3];
__device__ __align__(16) float g_T0[NROW * 2 * H_DIM];
__device__ __align__(16) float g_PREV[(size_t)S_DIM * NROW * DPAD];
__device__ __align__(16) float g_HA[(size_t)S_DIM * NROW * H_DIM];
__device__ __align__(16) float g_Y[(size_t)TROW * DPAD];
__device__ __align__(16) float g_W1C[G3 * C_DIM];
__device__ __align__(16) float g_W1P[G3 * DPAD];
__device__ __align__(16) float g_CR[NROW * C_DIM];
__device__ __align__(16) float g_FIW[2 * H_DIM * C_DIM];
__device__ __align__(16) float g_RW1H[G3 * H_DIM];
__device__ __align__(16) float g_RW2I[G3 * H_DIM];
__device__ __align__(16) float g_RW2H[G3 * H_DIM];
__device__ __align__(16) float g_RFO[D_DIM * H_DIM];

// ---------------- helpers ----------------------------------------------------
__device__ __forceinline__ float f2tf32(float x) {
    unsigned r;
    asm("cvt.rna.tf32.f32 %0, %1;" : "=r"(r) : "f"(x));
    return __uint_as_float(r);
}
__device__ __forceinline__ uint32_t smem_u32(const void* p) {
    uint32_t a;
    asm("{ .reg .u64 t; cvta.to.shared.u64 t, %1; cvt.u32.u64 %0, t; }"
        : "=r"(a) : "l"(p));
    return a;
}
__device__ __forceinline__ void mma_tf32(float d[4], const float a[4],
                                         const float b[2]) {
    asm volatile(
        "mma.sync.aligned.m16n8k8.row.col.f32.tf32.tf32.f32 "
        "{%0,%1,%2,%3}, {%4,%5,%6,%7}, {%8,%9}, {%0,%1,%2,%3};\n"
        : "+f"(d[0]), "+f"(d[1]), "+f"(d[2]), "+f"(d[3])
        : "r"(__float_as_uint(a[0])), "r"(__float_as_uint(a[1])),
          "r"(__float_as_uint(a[2])), "r"(__float_as_uint(a[3])),
          "r"(__float_as_uint(b[0])), "r"(__float_as_uint(b[1])));
}

// ---------------- z-batched TN GEMM params -----------------------------------
struct GP {
    const float *A, *B, *bias;
    float *C;
    int lda, ldb, ldc, K, N;
};

#define BKK 16
#define SR  20                       // smem row stride (floats), conflict-free
#define STAGE_F (2 * 128 * SR)       // floats per stage (A tile + B tile)
#define ER  136                      // epilogue transpose row stride (floats)
#define GSMEM_BYTES (4 * STAGE_F * 4)  // 81920 B (epilogue 128*136*4 fits)

// C[M,N] = A[M,K] * B[N,K]^T (+bias).  M mult of 128. 128x128x16 tile,
// 4 warps (64x64 warp tiles), 4-stage cp.async, smem-transpose epilogue.
__global__ void __launch_bounds__(128, 2) gemm4(GP p0, GP p1, GP p2)
{
    extern __shared__ float sm[];
    const GP p = (blockIdx.z == 0) ? p0 : ((blockIdx.z == 1) ? p1 : p2);
    const uint32_t smb = smem_u32(sm);
    const int tid  = threadIdx.x, lane = tid & 31, warp = tid >> 5;
    const int g    = lane >> 2, tg = lane & 3;
    const int wm   = (warp & 1) * 64, wn = (warp >> 1) * 64;
    const int bm0  = blockIdx.y * 128, bn0 = blockIdx.x * 128;
    const int KT   = (p.K + BKK - 1) / BKK;
    const int lrow = tid >> 2, lcg = (tid & 3) * 4;

    float acc[4][8][4];
#pragma unroll
    for (int mi = 0; mi < 4; mi++)
#pragma unroll
        for (int ni = 0; ni < 8; ni++)
#pragma unroll
            for (int f = 0; f < 4; f++) acc[mi][ni][f] = 0.f;

#define LOADS(kt, st) do {                                                    \
    uint32_t ab = smb + (uint32_t)((st) * STAGE_F) * 4u;                      \
    uint32_t bb = ab + 128u * SR * 4u;                                        \
    int kc = (kt) * BKK + lcg;                                                \
    _Pragma("unroll") for (int t = 0; t < 4; t++) {                           \
        int row = t * 32 + lrow;                                              \
        int sza = (kc < p.K) ? 16 : 0;                                        \
        const float* sa = sza ? (p.A + (size_t)(bm0 + row) * p.lda + kc)      \
                              : p.A;                                          \
        uint32_t da = ab + (uint32_t)(row * SR + lcg) * 4u;                   \
        asm volatile("cp.async.cg.shared.global [%0], [%1], 16, %2;"          \
                     :: "r"(da), "l"(sa), "r"(sza));                          \
        int gr = bn0 + row;                                                   \
        int szb = (kc < p.K && gr < p.N) ? 16 : 0;                            \
        const float* sb = szb ? (p.B + (size_t)gr * p.ldb + kc) : p.B;        \
        uint32_t db = bb + (uint32_t)(row * SR + lcg) * 4u;                   \
        asm volatile("cp.async.cg.shared.global [%0], [%1], 16, %2;"          \
                     :: "r"(db), "l"(sb), "r"(szb));                          \
    }                                                                         \
} while (0)

#define COMP(st) do {                                                         \
    const float* As = sm + (st) * STAGE_F;                                    \
    const float* Bs = As + 128 * SR;                                          \
    _Pragma("unroll") for (int s8 = 0; s8 < 2; s8++) {                        \
        const int k0 = s8 * 8;                                                \
        float af[4][4], bf[8][2];                                             \
        _Pragma("unroll") for (int mi = 0; mi < 4; mi++) {                    \
            int r = wm + mi * 16 + g;                                         \
            af[mi][0] = As[r * SR + k0 + tg];                                 \
            af[mi][1] = As[(r + 8) * SR + k0 + tg];                           \
            af[mi][2] = As[r * SR + k0 + tg + 4];                             \
            af[mi][3] = As[(r + 8) * SR + k0 + tg + 4];                       \
        }                                                                     \
        _Pragma("unroll") for (int ni = 0; ni < 8; ni++) {                    \
            int r = wn + ni * 8 + g;                                          \
            bf[ni][0] = Bs[r * SR + k0 + tg];                                 \
            bf[ni][1] = Bs[r * SR + k0 + tg + 4];                             \
        }                                                                     \
        _Pragma("unroll") for (int mi = 0; mi < 4; mi++)                      \
            _Pragma("unroll") for (int ni = 0; ni < 8; ni++)                  \
                mma_tf32(acc[mi][ni], af[mi], bf[ni]);                        \
    }                                                                         \
} while (0)

    // prologue: stages 0..2 (commit always, to keep group accounting fixed)
#pragma unroll
    for (int s = 0; s < 3; s++) {
        if (s < KT) LOADS(s, s);
        asm volatile("cp.async.commit_group;" ::: "memory");
    }
    for (int kt = 0; kt < KT; kt++) {
        asm volatile("cp.async.wait_group 2;" ::: "memory");
        __syncthreads();
        COMP(kt & 3);
        int nk = kt + 3;
        if (nk < KT) LOADS(nk, nk & 3);
        asm volatile("cp.async.commit_group;" ::: "memory");
        // next iteration's wait+sync protects stage reuse
        if (kt + 1 < KT) { } else { asm volatile("cp.async.wait_group 0;" ::: "memory"); }
        if (kt + 1 < KT) continue;
    }
#undef LOADS
#undef COMP

    // ---------------- epilogue: transpose through smem, coalesced stores -----
    __syncthreads();                 // all compute done; reuse stage smem
    float* smT = sm;
#pragma unroll
    for (int mi = 0; mi < 4; mi++)
#pragma unroll
        for (int ni = 0; ni < 8; ni++) {
            int r = wm + mi * 16 + g, cc = wn + ni * 8 + 2 * tg;
            *(float2*)&smT[r * ER + cc] =
                make_float2(acc[mi][ni][0], acc[mi][ni][1]);
            *(float2*)&smT[(r + 8) * ER + cc] =
                make_float2(acc[mi][ni][2], acc[mi][ni][3]);
        }
    __syncthreads();

    const int col = (tid & 31) * 4;
    const int rb  = tid >> 5;
    const int gn  = bn0 + col;
    float4 bv = make_float4(0.f, 0.f, 0.f, 0.f);
    if (p.bias) {
        if (gn < p.N)     bv.x = p.bias[gn];
        if (gn + 1 < p.N) bv.y = p.bias[gn + 1];
        if (gn + 2 < p.N) bv.z = p.bias[gn + 2];
        if (gn + 3 < p.N) bv.w = p.bias[gn + 3];
    }
#pragma unroll
    for (int j = 0; j < 32; j++) {
        int r = j * 4 + rb;
        float4 v = *(float4*)&smT[r * ER + col];
        v.x += bv.x; v.y += bv.y; v.z += bv.z; v.w += bv.w;
        float* cp = p.C + (size_t)(bm0 + r) * p.ldc + gn;
        if (gn + 3 < p.N) {
            *(float4*)cp = v;
        } else {
            if (gn < p.N)     cp[0] = v.x;
            if (gn + 1 < p.N) cp[1] = v.y;
            if (gn + 2 < p.N) cp[2] = v.z;
        }
    }
}

// ---------------- elementwise kernels ----------------------------------------
__device__ __forceinline__ float sigf(float x) {
    return 1.f / (1.f + __expf(-x));
}

template <bool HAS_GI2, bool HAS_COPY>
__global__ void gate_kernel(const float4* __restrict__ gi1,
                            const float4* __restrict__ gi2,
                            const float4* __restrict__ gh,
                            float4* __restrict__ h,
                            float4* __restrict__ hcopy)
{
    int v = blockIdx.x * blockDim.x + threadIdx.x;
    int m = v >> 8, q = v & 255;
    int base = m * 768 + q;
    float4 ir = gi1[base], iz = gi1[base + 256], in = gi1[base + 512];
    if (HAS_GI2) {
        float4 a = gi2[base], b = gi2[base + 256], c = gi2[base + 512];
        ir.x += a.x; ir.y += a.y; ir.z += a.z; ir.w += a.w;
        iz.x += b.x; iz.y += b.y; iz.z += b.z; iz.w += b.w;
        in.x += c.x; in.y += c.y; in.z += c.z; in.w += c.w;
    }
    float4 hr = gh[base], hz = gh[base + 256], hn = gh[base + 512];
    float4 hv = h[v];
    float4 o;
#define GATE1(cmp)                                                            \
    { float r = sigf(ir.cmp + hr.cmp), z = sigf(iz.cmp + hz.cmp);             \
      float n = tanhf(in.cmp + r * hn.cmp);                                   \
      o.cmp = f2tf32((1.f - z) * n + z * hv.cmp); }
    GATE1(x) GATE1(y) GATE1(z) GATE1(w)
#undef GATE1
    h[v] = o;
    if (HAS_COPY) hcopy[v] = o;
}

__global__ void init_tanh(const float4* __restrict__ t0,
                          float4* __restrict__ h1, float4* __restrict__ h2)
{
    int v = blockIdx.x * blockDim.x + threadIdx.x;
    int m = v >> 8, q = v & 255;
    float4 a = t0[m * 512 + q];
    float4 b = t0[m * 512 + 256 + q];
    a.x = f2tf32(tanhf(a.x)); a.y = f2tf32(tanhf(a.y));
    a.z = f2tf32(tanhf(a.z)); a.w = f2tf32(tanhf(a.w));
    b.x = f2tf32(tanhf(b.x)); b.y = f2tf32(tanhf(b.y));
    b.z = f2tf32(tanhf(b.z)); b.w = f2tf32(tanhf(b.w));
    h1[v] = a;
    h2[v] = b;
}

__global__ void pack_prev(const float* __restrict__ target,
                          float* __restrict__ prev)
{
    int idx = blockIdx.x * blockDim.x + threadIdx.x;
    if (idx >= S_DIM * NROW * DPAD) return;
    int d = idx % DPAD;
    int r = (idx / DPAD) % NROW;
    int s = idx / (DPAD * NROW);
    int e = r >> 7, b = r & 127;
    int t = e * S_DIM + s;
    float val = 0.f;
    if (d < D_DIM && t != 0)
        val = f2tf32(target[((size_t)b * OUT_T + (t - 1)) * D_DIM + d]);
    prev[idx] = val;
}

__global__ void repack_w1(const float* __restrict__ w,
                          float* __restrict__ w1c, float* __restrict__ w1p)
{
    int idx = blockIdx.x * blockDim.x + threadIdx.x;
    const int T1 = G3 * C_DIM;
    const int T2 = G3 * DPAD;
    if (idx < T1) {
        int n = idx / C_DIM, k = idx % C_DIM;
        w1c[idx] = f2tf32(w[(size_t)n * (C_DIM + D_DIM) + k]);
    } else if (idx < T1 + T2) {
        int j = idx - T1;
        int n = j / DPAD, k = j % DPAD;
        w1p[j] = (k < D_DIM)
            ? f2tf32(w[(size_t)n * (C_DIM + D_DIM) + C_DIM + k]) : 0.f;
    }
}

__global__ void round_copy(const float* __restrict__ src,
                           float* __restrict__ dst, int n)
{
    int idx = blockIdx.x * blockDim.x + threadIdx.x;
    if (idx < n) dst[idx] = f2tf32(src[idx]);
}

__global__ void scatter_out(const float* __restrict__ y,
                            float* __restrict__ out)
{
    int idx = blockIdx.x * blockDim.x + threadIdx.x;
    if (idx >= TROW * D_DIM) return;
    int d = idx % D_DIM;
    int m = idx / D_DIM;
    int s = m >> 11;
    int r = m & 2047;
    int e = r >> 7, b = r & 127;
    out[((size_t)b * OUT_T + e * S_DIM + s) * D_DIM + d] =
        y[(size_t)m * DPAD + d];
}

// ---------------- launch helpers ---------------------------------------------
static inline GP mk(const float* A, int lda, const float* B, int ldb,
                    const float* bias, float* C, int ldc, int K, int N)
{
    GP p;
    p.A = A; p.B = B; p.bias = bias; p.C = C;
    p.lda = lda; p.ldb = ldb; p.ldc = ldc; p.K = K; p.N = N;
    return p;
}
static inline void launch_gemm(GP p0, GP p1, GP p2, int M, int Nmax, int nz)
{
    cudaFuncSetAttribute(gemm4, cudaFuncAttributeMaxDynamicSharedMemorySize,
                         GSMEM_BYTES);
    dim3 grid((Nmax + 127) / 128, M / 128, nz);
    gemm4<<<grid, 128, GSMEM_BYTES>>>(p0, p1, p2);
}

extern "C" void kernel_launch(void* const* d_in, const int* in_sizes, int n_in,
                              void* d_out, int out_size)
{
    const float* c      = (const float*)d_in[0];
    const float* target = (const float*)d_in[1];
    int base = (n_in >= 16) ? 4 : 2;
    const float* fc_init_w = (const float*)d_in[base + 0];
    const float* fc_init_b = (const float*)d_in[base + 1];
    const float* g1_wih    = (const float*)d_in[base + 2];
    const float* g1_whh    = (const float*)d_in[base + 3];
    const float* g1_bih    = (const float*)d_in[base + 4];
    const float* g1_bhh    = (const float*)d_in[base + 5];
    const float* g2_wih    = (const float*)d_in[base + 6];
    const float* g2_whh    = (const float*)d_in[base + 7];
    const float* g2_bih    = (const float*)d_in[base + 8];
    const float* g2_bhh    = (const float*)d_in[base + 9];
    const float* fco_w     = (const float*)d_in[base + 10];
    const float* fco_b     = (const float*)d_in[base + 11];
    float* out = (float*)d_out;

    float *H1, *H2, *TA, *TB, *PPs, *CP, *T0, *PV, *HA, *Y, *W1C, *W1P;
    float *CR, *FIW, *RW1H, *RW2I, *RW2H, *RFO;
    cudaGetSymbolAddress((void**)&H1, g_H1);
    cudaGetSymbolAddress((void**)&H2, g_H2);
    cudaGetSymbolAddress((void**)&TA, g_TA);
    cudaGetSymbolAddress((void**)&TB, g_TB);
    cudaGetSymbolAddress((void**)&PPs, g_PPs);
    cudaGetSymbolAddress((void**)&CP, g_CP);
    cudaGetSymbolAddress((void**)&T0, g_T0);
    cudaGetSymbolAddress((void**)&PV, g_PREV);
    cudaGetSymbolAddress((void**)&HA, g_HA);
    cudaGetSymbolAddress((void**)&Y,  g_Y);
    cudaGetSymbolAddress((void**)&W1C, g_W1C);
    cudaGetSymbolAddress((void**)&W1P, g_W1P);
    cudaGetSymbolAddress((void**)&CR,  g_CR);
    cudaGetSymbolAddress((void**)&FIW, g_FIW);
    cudaGetSymbolAddress((void**)&RW1H, g_RW1H);
    cudaGetSymbolAddress((void**)&RW2I, g_RW2I);
    cudaGetSymbolAddress((void**)&RW2H, g_RW2H);
    cudaGetSymbolAddress((void**)&RFO,  g_RFO);

    // ---- precompute ----
    repack_w1<<<(G3 * (C_DIM + DPAD) + 255) / 256, 256>>>(g1_wih, W1C, W1P);
    pack_prev<<<(S_DIM * NROW * DPAD + 255) / 256, 256>>>(target, PV);
    round_copy<<<(NROW * C_DIM + 255) / 256, 256>>>(c, CR, NROW * C_DIM);
    round_copy<<<(2 * H_DIM * C_DIM + 255) / 256, 256>>>(fc_init_w, FIW,
                                                         2 * H_DIM * C_DIM);
    round_copy<<<(G3 * H_DIM + 255) / 256, 256>>>(g1_whh, RW1H, G3 * H_DIM);
    round_copy<<<(G3 * H_DIM + 255) / 256, 256>>>(g2_wih, RW2I, G3 * H_DIM);
    round_copy<<<(G3 * H_DIM + 255) / 256, 256>>>(g2_whh, RW2H, G3 * H_DIM);
    round_copy<<<(D_DIM * H_DIM + 255) / 256, 256>>>(fco_w, RFO, D_DIM * H_DIM);

    // cpart = c @ W1C^T + g1_bih            [2048 x 3072]
    {
        GP p = mk(CR, C_DIM, W1C, C_DIM, g1_bih, CP, G3, C_DIM, G3);
        launch_gemm(p, p, p, NROW, G3, 1);
    }
    // t0 = c @ fc_init_w^T + fc_init_b      [2048 x 2048]
    {
        GP p = mk(CR, C_DIM, FIW, C_DIM, fc_init_b, T0, 2 * H_DIM,
                  C_DIM, 2 * H_DIM);
        launch_gemm(p, p, p, NROW, 2 * H_DIM, 1);
    }
    init_tanh<<<(NROW * H_DIM / 4) / 256, 256>>>(
        (const float4*)T0, (float4*)H1, (float4*)H2);

    // ---- recurrent loop ----
    for (int s = 0; s < S_DIM; s++) {
        // z0: gh1 = h1@g1_whh^T + g1_bhh ; z1: gh2 = h2@g2_whh^T + g2_bhh
        // z2: PPs = prev[s]@W1P^T  (input-side n/r/z contribution, per step)
        GP p0 = mk(H1, H_DIM, RW1H, H_DIM, g1_bhh, TA, G3, H_DIM, G3);
        GP p1 = mk(H2, H_DIM, RW2H, H_DIM, g2_bhh, TB, G3, H_DIM, G3);
        GP p2 = mk(PV + (size_t)s * NROW * DPAD, DPAD, W1P, DPAD, nullptr,
                   PPs, G3, DPAD, G3);
        launch_gemm(p0, p1, p2, NROW, G3, 3);
        gate_kernel<true, false><<<(NROW * H_DIM / 4) / 256, 256>>>(
            (const float4*)CP, (const float4*)PPs,
            (const float4*)TA, (float4*)H1, nullptr);
        GP pg = mk(H1, H_DIM, RW2I, H_DIM, g2_bih, TA, G3, H_DIM, G3);
        launch_gemm(pg, pg, pg, NROW, G3, 1);
        gate_kernel<false, true><<<(NROW * H_DIM / 4) / 256, 256>>>(
            (const float4*)TA, nullptr, (const float4*)TB,
            (float4*)H2, (float4*)(HA + (size_t)s * NROW * H_DIM));
    }

    // ---- output projection + scatter ----
    {
        GP p = mk(HA, H_DIM, RFO, H_DIM, fco_b, Y, DPAD, H_DIM, D_DIM);
        launch_gemm(p, p, p, TROW, D_DIM, 1);
    }
    scatter_out<<<(TROW * D_DIM + 255) / 256, 256>>>(Y, out);
}

// round 6
// speedup vs baseline: 2.5925x; 1.8091x over previous
#include <cuda_runtime.h>
#include <cuda_fp16.h>
#include <cstdint>
#include <cstddef>

#define E_DIM 16
#define B_DIM 128
#define C_DIM 512
#define H_DIM 1024
#define D_DIM 130
#define DPAD  132            // fp32 Y row pad
#define DPH   136            // half prev row pad (16B-aligned rows)
#define S_DIM 16
#define NROW  2048
#define G3    3072
#define TROW  32768
#define OUT_T 256

// ---------------- scratch (static device globals) ----------------------------
// half operands
__device__ __align__(16) __half g_H1h[NROW * H_DIM];
__device__ __align__(16) __half g_H2h[NROW * H_DIM];
__device__ __align__(16) __half g_HAh[(size_t)S_DIM * NROW * H_DIM];
__device__ __align__(16) __half g_PVh[(size_t)S_DIM * NROW * DPH];
__device__ __align__(16) __half g_CRh[NROW * C_DIM];
__device__ __align__(16) __half g_FIWh[2 * H_DIM * C_DIM];
__device__ __align__(16) __half g_W1Ch[G3 * C_DIM];
__device__ __align__(16) __half g_W1Ph[G3 * DPH];
__device__ __align__(16) __half g_W1Hh[G3 * H_DIM];
__device__ __align__(16) __half g_W2Ih[G3 * H_DIM];
__device__ __align__(16) __half g_W2Hh[G3 * H_DIM];
__device__ __align__(16) __half g_FOh[D_DIM * H_DIM];
// fp32 GEMM outputs
__device__ __align__(16) float g_TA[NROW * G3];
__device__ __align__(16) float g_TB[NROW * G3];
__device__ __align__(16) float g_PPs[NROW * G3];
__device__ __align__(16) float g_CP[NROW * G3];
__device__ __align__(16) float g_T0[NROW * 2 * H_DIM];
__device__ __align__(16) float g_Y[(size_t)TROW * DPAD];

// ---------------- helpers ----------------------------------------------------
__device__ __forceinline__ uint32_t smem_u32(const void* p) {
    uint32_t a;
    asm("{ .reg .u64 t; cvta.to.shared.u64 t, %1; cvt.u32.u64 %0, t; }"
        : "=r"(a) : "l"(p));
    return a;
}
__device__ __forceinline__ void mma_f16(float d[4], const uint32_t a[4],
                                        const uint32_t b[2]) {
    asm volatile(
        "mma.sync.aligned.m16n8k16.row.col.f32.f16.f16.f32 "
        "{%0,%1,%2,%3}, {%4,%5,%6,%7}, {%8,%9}, {%0,%1,%2,%3};\n"
        : "+f"(d[0]), "+f"(d[1]), "+f"(d[2]), "+f"(d[3])
        : "r"(a[0]), "r"(a[1]), "r"(a[2]), "r"(a[3]), "r"(b[0]), "r"(b[1]));
}

// ---------------- z-batched TN GEMM (half operands, fp32 out) ----------------
struct GP {
    const __half *A, *B;
    const float* bias;
    float* C;
    int lda, ldb, ldc, K, N;
};

#define RS   40                      // smem row stride in halves (80 B)
#define STG_B 20480                  // bytes per stage (A 10240 + B 10240)
#define ER   136                     // epilogue fp32 row stride
#define GSMEM_BYTES (4 * STG_B)      // 81920 (epilogue 128*136*4=69632 fits)

// C[M,N] = A[M,K] * B[N,K]^T (+bias). M mult of 128. Tile 128x128x32(half),
// 4 warps (64x64), 4-stage cp.async, smem-transpose coalesced epilogue.
__global__ void __launch_bounds__(128, 2) gemm4(GP p0, GP p1, GP p2)
{
    extern __shared__ __half smh[];
    float* smf = (float*)smh;
    const GP p = (blockIdx.z == 0) ? p0 : ((blockIdx.z == 1) ? p1 : p2);
    const uint32_t smb = smem_u32(smh);
    const int tid  = threadIdx.x, lane = tid & 31, warp = tid >> 5;
    const int g    = lane >> 2, tg = lane & 3;
    const int wm   = (warp & 1) * 64, wn = (warp >> 1) * 64;
    const int bm0  = blockIdx.y * 128, bn0 = blockIdx.x * 128;
    const int KT   = (p.K + 31) / 32;
    const int lrow = tid >> 2, ci = tid & 3;   // 4 x 16B chunks per 64B row

    float acc[4][8][4];
#pragma unroll
    for (int mi = 0; mi < 4; mi++)
#pragma unroll
        for (int ni = 0; ni < 8; ni++)
#pragma unroll
            for (int f = 0; f < 4; f++) acc[mi][ni][f] = 0.f;

#define LOADS(kt, st) do {                                                    \
    uint32_t ab = smb + (uint32_t)(st) * STG_B;                               \
    uint32_t bb = ab + STG_B / 2;                                             \
    int kc = (kt) * 32 + ci * 8;                                              \
    int sza = (kc < p.K) ? 16 : 0;                                            \
    _Pragma("unroll") for (int t = 0; t < 4; t++) {                           \
        int row = t * 32 + lrow;                                              \
        const __half* sa = sza ? (p.A + (size_t)(bm0 + row) * p.lda + kc)     \
                               : p.A;                                         \
        uint32_t da = ab + (uint32_t)(row * 80 + ci * 16);                    \
        asm volatile("cp.async.cg.shared.global [%0], [%1], 16, %2;"          \
                     :: "r"(da), "l"(sa), "r"(sza));                          \
        int gr = bn0 + row;                                                   \
        int szb = (sza && gr < p.N) ? 16 : 0;                                 \
        const __half* sb = szb ? (p.B + (size_t)gr * p.ldb + kc) : p.B;       \
        uint32_t db = bb + (uint32_t)(row * 80 + ci * 16);                    \
        asm volatile("cp.async.cg.shared.global [%0], [%1], 16, %2;"          \
                     :: "r"(db), "l"(sb), "r"(szb));                          \
    }                                                                         \
} while (0)

#define COMP(st) do {                                                         \
    const __half* As = smh + (size_t)(st) * (STG_B / 2);                      \
    const __half* Bs = As + STG_B / 4;                                        \
    _Pragma("unroll") for (int ks = 0; ks < 2; ks++) {                        \
        const int k0 = ks * 16 + tg * 2;                                      \
        uint32_t af[4][4], bf[8][2];                                          \
        _Pragma("unroll") for (int mi = 0; mi < 4; mi++) {                    \
            int r = wm + mi * 16 + g;                                         \
            af[mi][0] = *(const uint32_t*)&As[r * RS + k0];                   \
            af[mi][1] = *(const uint32_t*)&As[(r + 8) * RS + k0];             \
            af[mi][2] = *(const uint32_t*)&As[r * RS + k0 + 8];               \
            af[mi][3] = *(const uint32_t*)&As[(r + 8) * RS + k0 + 8];         \
        }                                                                     \
        _Pragma("unroll") for (int ni = 0; ni < 8; ni++) {                    \
            int n = wn + ni * 8 + g;                                          \
            bf[ni][0] = *(const uint32_t*)&Bs[n * RS + k0];                   \
            bf[ni][1] = *(const uint32_t*)&Bs[n * RS + k0 + 8];               \
        }                                                                     \
        _Pragma("unroll") for (int mi = 0; mi < 4; mi++)                      \
            _Pragma("unroll") for (int ni = 0; ni < 8; ni++)                  \
                mma_f16(acc[mi][ni], af[mi], bf[ni]);                         \
    }                                                                         \
} while (0)

#pragma unroll
    for (int s = 0; s < 3; s++) {
        if (s < KT) LOADS(s, s);
        asm volatile("cp.async.commit_group;" ::: "memory");
    }
    for (int kt = 0; kt < KT; kt++) {
        asm volatile("cp.async.wait_group 2;" ::: "memory");
        __syncthreads();
        COMP(kt & 3);
        int nk = kt + 3;
        if (nk < KT) LOADS(nk, nk & 3);
        asm volatile("cp.async.commit_group;" ::: "memory");
    }
    asm volatile("cp.async.wait_group 0;" ::: "memory");
#undef LOADS
#undef COMP

    // ---- epilogue: fp32 acc -> smem transpose -> coalesced stores (+bias) ---
    __syncthreads();
#pragma unroll
    for (int mi = 0; mi < 4; mi++)
#pragma unroll
        for (int ni = 0; ni < 8; ni++) {
            int r = wm + mi * 16 + g, cc = wn + ni * 8 + 2 * tg;
            *(float2*)&smf[r * ER + cc] =
                make_float2(acc[mi][ni][0], acc[mi][ni][1]);
            *(float2*)&smf[(r + 8) * ER + cc] =
                make_float2(acc[mi][ni][2], acc[mi][ni][3]);
        }
    __syncthreads();

    const int col = (tid & 31) * 4;
    const int rb  = tid >> 5;
    const int gn  = bn0 + col;
    float4 bv = make_float4(0.f, 0.f, 0.f, 0.f);
    if (p.bias) {
        if (gn < p.N)     bv.x = p.bias[gn];
        if (gn + 1 < p.N) bv.y = p.bias[gn + 1];
        if (gn + 2 < p.N) bv.z = p.bias[gn + 2];
        if (gn + 3 < p.N) bv.w = p.bias[gn + 3];
    }
#pragma unroll
    for (int j = 0; j < 32; j++) {
        int r = j * 4 + rb;
        float4 v = *(float4*)&smf[r * ER + col];
        v.x += bv.x; v.y += bv.y; v.z += bv.z; v.w += bv.w;
        float* cp = p.C + (size_t)(bm0 + r) * p.ldc + gn;
        if (gn + 3 < p.N) {
            *(float4*)cp = v;
        } else {
            if (gn < p.N)     cp[0] = v.x;
            if (gn + 1 < p.N) cp[1] = v.y;
            if (gn + 2 < p.N) cp[2] = v.z;
        }
    }
}

// ---------------- elementwise kernels ----------------------------------------
__device__ __forceinline__ float sigf(float x) {
    return 1.f / (1.f + __expf(-x));
}

// gi = gi1 (+gi2); h' = (1-z)*n + z*h. h stored as half (4 units/thread).
template <bool HAS_GI2, bool HAS_COPY>
__global__ void gate_kernel(const float4* __restrict__ gi1,
                            const float4* __restrict__ gi2,
                            const float4* __restrict__ gh,
                            __half2* __restrict__ h,
                            __half2* __restrict__ hcopy)
{
    int v = blockIdx.x * blockDim.x + threadIdx.x;
    int m = v >> 8, q = v & 255;
    int base = m * 768 + q;
    float4 ir = gi1[base], iz = gi1[base + 256], in = gi1[base + 512];
    if (HAS_GI2) {
        float4 a = gi2[base], b = gi2[base + 256], c = gi2[base + 512];
        ir.x += a.x; ir.y += a.y; ir.z += a.z; ir.w += a.w;
        iz.x += b.x; iz.y += b.y; iz.z += b.z; iz.w += b.w;
        in.x += c.x; in.y += c.y; in.z += c.z; in.w += c.w;
    }
    float4 hr = gh[base], hz = gh[base + 256], hn = gh[base + 512];
    __half2 h0 = h[2 * v], h1 = h[2 * v + 1];
    float4 hv = make_float4(__low2float(h0), __high2float(h0),
                            __low2float(h1), __high2float(h1));
    float4 o;
#define GATE1(cmp)                                                            \
    { float r = sigf(ir.cmp + hr.cmp), z = sigf(iz.cmp + hz.cmp);             \
      float n = tanhf(in.cmp + r * hn.cmp);                                   \
      o.cmp = (1.f - z) * n + z * hv.cmp; }
    GATE1(x) GATE1(y) GATE1(z) GATE1(w)
#undef GATE1
    __half2 o0 = __floats2half2_rn(o.x, o.y);
    __half2 o1 = __floats2half2_rn(o.z, o.w);
    h[2 * v] = o0;
    h[2 * v + 1] = o1;
    if (HAS_COPY) {
        hcopy[2 * v] = o0;
        hcopy[2 * v + 1] = o1;
    }
}

__global__ void init_tanh(const float4* __restrict__ t0,
                          __half2* __restrict__ h1, __half2* __restrict__ h2)
{
    int v = blockIdx.x * blockDim.x + threadIdx.x;
    int m = v >> 8, q = v & 255;
    float4 a = t0[m * 512 + q];
    float4 b = t0[m * 512 + 256 + q];
    h1[2 * v]     = __floats2half2_rn(tanhf(a.x), tanhf(a.y));
    h1[2 * v + 1] = __floats2half2_rn(tanhf(a.z), tanhf(a.w));
    h2[2 * v]     = __floats2half2_rn(tanhf(b.x), tanhf(b.y));
    h2[2 * v + 1] = __floats2half2_rn(tanhf(b.z), tanhf(b.w));
}

__global__ void pack_prev(const float* __restrict__ target,
                          __half* __restrict__ prev)
{
    int idx = blockIdx.x * blockDim.x + threadIdx.x;
    if (idx >= S_DIM * NROW * DPH) return;
    int d = idx % DPH;
    int r = (idx / DPH) % NROW;
    int s = idx / (DPH * NROW);
    int e = r >> 7, b = r & 127;
    int t = e * S_DIM + s;
    float val = 0.f;
    if (d < D_DIM && t != 0)
        val = target[((size_t)b * OUT_T + (t - 1)) * D_DIM + d];
    prev[idx] = __float2half(val);
}

__global__ void repack_w1(const float* __restrict__ w,
                          __half* __restrict__ w1c, __half* __restrict__ w1p)
{
    int idx = blockIdx.x * blockDim.x + threadIdx.x;
    const int T1 = G3 * C_DIM;
    const int T2 = G3 * DPH;
    if (idx < T1) {
        int n = idx / C_DIM, k = idx % C_DIM;
        w1c[idx] = __float2half(w[(size_t)n * (C_DIM + D_DIM) + k]);
    } else if (idx < T1 + T2) {
        int j = idx - T1;
        int n = j / DPH, k = j % DPH;
        w1p[j] = __float2half(
            (k < D_DIM) ? w[(size_t)n * (C_DIM + D_DIM) + C_DIM + k] : 0.f);
    }
}

__global__ void half_copy(const float* __restrict__ src,
                          __half* __restrict__ dst, int n)
{
    int idx = blockIdx.x * blockDim.x + threadIdx.x;
    if (idx < n) dst[idx] = __float2half(src[idx]);
}

__global__ void scatter_out(const float* __restrict__ y,
                            float* __restrict__ out)
{
    int idx = blockIdx.x * blockDim.x + threadIdx.x;
    if (idx >= TROW * D_DIM) return;
    int d = idx % D_DIM;
    int m = idx / D_DIM;
    int s = m >> 11;
    int r = m & 2047;
    int e = r >> 7, b = r & 127;
    out[((size_t)b * OUT_T + e * S_DIM + s) * D_DIM + d] =
        y[(size_t)m * DPAD + d];
}

// ---------------- launch helpers ---------------------------------------------
static inline GP mk(const __half* A, int lda, const __half* B, int ldb,
                    const float* bias, float* C, int ldc, int K, int N)
{
    GP p;
    p.A = A; p.B = B; p.bias = bias; p.C = C;
    p.lda = lda; p.ldb = ldb; p.ldc = ldc; p.K = K; p.N = N;
    return p;
}
static inline void launch_gemm(GP p0, GP p1, GP p2, int M, int Nmax, int nz)
{
    cudaFuncSetAttribute(gemm4, cudaFuncAttributeMaxDynamicSharedMemorySize,
                         GSMEM_BYTES);
    dim3 grid((Nmax + 127) / 128, M / 128, nz);
    gemm4<<<grid, 128, GSMEM_BYTES>>>(p0, p1, p2);
}

extern "C" void kernel_launch(void* const* d_in, const int* in_sizes, int n_in,
                              void* d_out, int out_size)
{
    const float* c      = (const float*)d_in[0];
    const float* target = (const float*)d_in[1];
    int base = (n_in >= 16) ? 4 : 2;
    const float* fc_init_w = (const float*)d_in[base + 0];
    const float* fc_init_b = (const float*)d_in[base + 1];
    const float* g1_wih    = (const float*)d_in[base + 2];
    const float* g1_whh    = (const float*)d_in[base + 3];
    const float* g1_bih    = (const float*)d_in[base + 4];
    const float* g1_bhh    = (const float*)d_in[base + 5];
    const float* g2_wih    = (const float*)d_in[base + 6];
    const float* g2_whh    = (const float*)d_in[base + 7];
    const float* g2_bih    = (const float*)d_in[base + 8];
    const float* g2_bhh    = (const float*)d_in[base + 9];
    const float* fco_w     = (const float*)d_in[base + 10];
    const float* fco_b     = (const float*)d_in[base + 11];
    float* out = (float*)d_out;

    __half *H1h, *H2h, *HAh, *PVh, *CRh, *FIWh, *W1Ch, *W1Ph, *W1Hh, *W2Ih,
        *W2Hh, *FOh;
    float *TA, *TB, *PPs, *CP, *T0, *Y;
    cudaGetSymbolAddress((void**)&H1h, g_H1h);
    cudaGetSymbolAddress((void**)&H2h, g_H2h);
    cudaGetSymbolAddress((void**)&HAh, g_HAh);
    cudaGetSymbolAddress((void**)&PVh, g_PVh);
    cudaGetSymbolAddress((void**)&CRh, g_CRh);
    cudaGetSymbolAddress((void**)&FIWh, g_FIWh);
    cudaGetSymbolAddress((void**)&W1Ch, g_W1Ch);
    cudaGetSymbolAddress((void**)&W1Ph, g_W1Ph);
    cudaGetSymbolAddress((void**)&W1Hh, g_W1Hh);
    cudaGetSymbolAddress((void**)&W2Ih, g_W2Ih);
    cudaGetSymbolAddress((void**)&W2Hh, g_W2Hh);
    cudaGetSymbolAddress((void**)&FOh, g_FOh);
    cudaGetSymbolAddress((void**)&TA, g_TA);
    cudaGetSymbolAddress((void**)&TB, g_TB);
    cudaGetSymbolAddress((void**)&PPs, g_PPs);
    cudaGetSymbolAddress((void**)&CP, g_CP);
    cudaGetSymbolAddress((void**)&T0, g_T0);
    cudaGetSymbolAddress((void**)&Y,  g_Y);

    // ---- precompute: convert operands to half ----
    repack_w1<<<(G3 * (C_DIM + DPH) + 255) / 256, 256>>>(g1_wih, W1Ch, W1Ph);
    pack_prev<<<(S_DIM * NROW * DPH + 255) / 256, 256>>>(target, PVh);
    half_copy<<<(NROW * C_DIM + 255) / 256, 256>>>(c, CRh, NROW * C_DIM);
    half_copy<<<(2 * H_DIM * C_DIM + 255) / 256, 256>>>(fc_init_w, FIWh,
                                                        2 * H_DIM * C_DIM);
    half_copy<<<(G3 * H_DIM + 255) / 256, 256>>>(g1_whh, W1Hh, G3 * H_DIM);
    half_copy<<<(G3 * H_DIM + 255) / 256, 256>>>(g2_wih, W2Ih, G3 * H_DIM);
    half_copy<<<(G3 * H_DIM + 255) / 256, 256>>>(g2_whh, W2Hh, G3 * H_DIM);
    half_copy<<<(D_DIM * H_DIM + 255) / 256, 256>>>(fco_w, FOh, D_DIM * H_DIM);

    // cpart = c @ W1C^T + g1_bih  [2048x3072];  t0 = c @ fiw^T + b [2048x2048]
    {
        GP p = mk(CRh, C_DIM, W1Ch, C_DIM, g1_bih, CP, G3, C_DIM, G3);
        launch_gemm(p, p, p, NROW, G3, 1);
    }
    {
        GP p = mk(CRh, C_DIM, FIWh, C_DIM, fc_init_b, T0, 2 * H_DIM,
                  C_DIM, 2 * H_DIM);
        launch_gemm(p, p, p, NROW, 2 * H_DIM, 1);
    }
    init_tanh<<<(NROW * H_DIM / 4) / 256, 256>>>(
        (const float4*)T0, (__half2*)H1h, (__half2*)H2h);

    // ---- recurrent loop ----
    for (int s = 0; s < S_DIM; s++) {
        GP p0 = mk(H1h, H_DIM, W1Hh, H_DIM, g1_bhh, TA, G3, H_DIM, G3);
        GP p1 = mk(H2h, H_DIM, W2Hh, H_DIM, g2_bhh, TB, G3, H_DIM, G3);
        GP p2 = mk(PVh + (size_t)s * NROW * DPH, DPH, W1Ph, DPH, nullptr,
                   PPs, G3, DPH, G3);
        launch_gemm(p0, p1, p2, NROW, G3, 3);
        gate_kernel<true, false><<<(NROW * H_DIM / 4) / 256, 256>>>(
            (const float4*)CP, (const float4*)PPs,
            (const float4*)TA, (__half2*)H1h, nullptr);
        GP pg = mk(H1h, H_DIM, W2Ih, H_DIM, g2_bih, TA, G3, H_DIM, G3);
        launch_gemm(pg, pg, pg, NROW, G3, 1);
        gate_kernel<false, true><<<(NROW * H_DIM / 4) / 256, 256>>>(
            (const float4*)TA, nullptr, (const float4*)TB,
            (__half2*)H2h, (__half2*)(HAh + (size_t)s * NROW * H_DIM));
    }

    // ---- output projection + scatter ----
    {
        GP p = mk(HAh, H_DIM, FOh, H_DIM, fco_b, Y, DPAD, H_DIM, D_DIM);
        launch_gemm(p, p, p, TROW, D_DIM, 1);
    }
    scatter_out<<<(TROW * D_DIM + 255) / 256, 256>>>(Y, out);
}